// round 7
// baseline (speedup 1.0000x reference)
#include <cuda_runtime.h>
#include <cstdint>

// Problem constants
#define MAX_DIST 35.0f
#define BOX 71            // ceil(2*35/1 + 1)
#define FDIM 32
#define BATCH 8
#define NPTS 16384

// Derived sizes (in float4 units)
#define SLICE0_F4 (BOX * BOX * BOX * FDIM / 4)          // 2,863,288
#define TOTAL_F4  (BATCH * BOX * BOX * BOX * FDIM / 4)  // 22,906,304
#define SCATTER_WORK (BATCH * NPTS * (FDIM / 4))        // 1,048,576 point-quads
#define NTHREADS SCATTER_WORK                           // 1 scatter item / thread

// Input sizes in 128B cache lines (for the L2 prefetch in kernel A)
#define COORD_BYTES (BATCH * NPTS * 3 * 4)              // 1,572,864
#define FEAT_BYTES  (BATCH * NPTS * FDIM * 4)           // 16,777,216
#define COORD_LINES (COORD_BYTES / 128)                 // 12,288
#define FEAT_LINES  (FEAT_BYTES / 128)                  // 131,072
#define PF_LINES    (COORD_LINES + FEAT_LINES)          // 143,360

#define A_BLOCKS (148 * 8)
#define A_THREADS (A_BLOCKS * 256)                      // 303,104

// ---------------------------------------------------------------------------
// Kernel A: zero batch slice 0 (45.8 MB) with streaming stores (evict-first:
// R4 measured this gives the fastest kernel B — resident slice 0 just defers
// its writebacks into B). A is store-issue bound, so its idle read bandwidth
// is used to PREFETCH the scatter inputs (coords + features, 17.5 MB) into
// L2: kernel B's loads then hit L2 and don't steal DRAM cycles from its
// store stream.
// ---------------------------------------------------------------------------
__global__ void __launch_bounds__(256)
zero_slice0_prefetch_kernel(float4* __restrict__ out,
                            const char* __restrict__ coords_bytes,
                            const char* __restrict__ feats_bytes) {
    const int t = blockIdx.x * blockDim.x + threadIdx.x;

    // One L2 prefetch line per thread (no register result, cannot be elided).
    if (t < PF_LINES) {
        const char* addr = (t < COORD_LINES)
                               ? coords_bytes + (size_t)t * 128
                               : feats_bytes + (size_t)(t - COORD_LINES) * 128;
        asm volatile("prefetch.global.L2 [%0];" :: "l"(addr));
    }

    const float4 z = make_float4(0.f, 0.f, 0.f, 0.f);
    for (int i = t; i < SLICE0_F4; i += A_THREADS) {
        __stcs(&out[i], z);
    }
}

// ---------------------------------------------------------------------------
// Kernel B (fused, R4-proven shape): 1,048,576 threads (4096 x 256).
//   Each thread:
//     1. issues its scatter input loads (now L2 hits thanks to kernel A),
//     2. streams zeros into slices 1..7 (__stcs evict-first),
//     3. fires one red.global.add.v4.f32 into batch slice 0 mid-stream,
//     4. finishes its zero stripe.
// Scatter semantics (faithful to the reference):
//   - ALL B*N points land in batch slice 0 (reference's tf.zeros batch column)
//   - round-half-to-even via __float2int_rn (jnp.round)
//   - out-of-box points contribute exactly +0.0 -> skipped
// ---------------------------------------------------------------------------
__global__ void __launch_bounds__(256)
fused_scatter_zero_kernel(const float* __restrict__ coords,
                          const float4* __restrict__ features4,
                          float* __restrict__ out) {
    const int tid = blockIdx.x * blockDim.x + threadIdx.x;

    const int p = tid >> 3;        // global point index (b*N + n)
    const int q = tid & 7;         // which float4 of the 8 covering F=32

    // Issue all scatter inputs NOW (L2 hits); consumed after 6 store batches.
    float c0 = __ldg(&coords[p * 3 + 0]);
    float c1 = __ldg(&coords[p * 3 + 1]);
    float c2 = __ldg(&coords[p * 3 + 2]);
    float4 v = __ldg(&features4[(long long)p * 8 + q]);

    float4* out4 = (float4*)out;
    const float4 z = make_float4(0.f, 0.f, 0.f, 0.f);

    long long i = (long long)SLICE0_F4 + tid;

    #pragma unroll
    for (int k = 0; k < 6; k++) {
        if (i < TOTAL_F4) { __stcs(&out4[i], z); }
        i += NTHREADS;
    }

    // Scatter: loads have landed; fire-and-forget vector reduction.
    {
        int g0 = __float2int_rn(c0 + MAX_DIST);
        int g1 = __float2int_rn(c1 + MAX_DIST);
        int g2 = __float2int_rn(c2 + MAX_DIST);
        if ((unsigned)g0 < BOX && (unsigned)g1 < BOX && (unsigned)g2 < BOX) {
            int cell = (g0 * BOX + g1) * BOX + g2;
            float* dst = out + (long long)cell * FDIM + q * 4;  // slice 0
            asm volatile("red.global.add.v4.f32 [%0], {%1, %2, %3, %4};"
                         :: "l"(dst), "f"(v.x), "f"(v.y), "f"(v.z), "f"(v.w)
                         : "memory");
        }
    }

    // Remaining zero stores.
    for (; i < TOTAL_F4; i += NTHREADS) {
        __stcs(&out4[i], z);
    }
}

extern "C" void kernel_launch(void* const* d_in, const int* in_sizes, int n_in,
                              void* d_out, int out_size) {
    const float* coords = (const float*)d_in[0];     // [8,16384,3] f32
    const float4* feats = (const float4*)d_in[1];    // [8,16384,32] f32 as float4
    float* out = (float*)d_out;                      // [8,71,71,71,32] f32

    // Kernel A: zero slice 0 + L2-prefetch the scatter inputs.
    zero_slice0_prefetch_kernel<<<A_BLOCKS, 256>>>(
        (float4*)out, (const char*)coords, (const char*)feats);

    // Kernel B: fused scatter + zero of slices 1..7.
    fused_scatter_zero_kernel<<<SCATTER_WORK / 256, 256>>>(coords, feats, out);
}

// round 8
// speedup vs baseline: 1.0350x; 1.0350x over previous
#include <cuda_runtime.h>
#include <cstdint>

// Problem constants
#define MAX_DIST 35.0f
#define BOX 71            // ceil(2*35/1 + 1)
#define FDIM 32
#define BATCH 8
#define NPTS 16384

// Derived sizes (in float4 units)
#define SLICE0_F4 (BOX * BOX * BOX * FDIM / 4)          // 2,863,288
#define TOTAL_F4  (BATCH * BOX * BOX * BOX * FDIM / 4)  // 22,906,304
#define SCATTER_WORK (BATCH * NPTS * (FDIM / 4))        // 1,048,576 point-quads
#define NTHREADS SCATTER_WORK                           // 1 scatter item / thread

#define A_BLOCKS (148 * 8)                              // one full wave
#define A_THREADS (A_BLOCKS * 256)

// ---------------------------------------------------------------------------
// Kernel A: zero batch slice 0 (45.8 MB) with STREAMING stores (__stcs,
// evict-first). Measured across rounds:
//   - memsetAsync:         A-step 9.8us (driver + launch gap)   [R4]
//   - plain stores:        A 7.6us but B +2.2us (deferred WBs)  [R6]
//   - __stcs + prefetch:   A 9.9us (prefetch reads on A's path) [R7]
// -> __stcs alone: A ~7.4us AND B keeps its best-measured shape.
// ---------------------------------------------------------------------------
__global__ void __launch_bounds__(256)
zero_slice0_kernel(float4* __restrict__ out) {
    const float4 z = make_float4(0.f, 0.f, 0.f, 0.f);
    for (int i = blockIdx.x * blockDim.x + threadIdx.x; i < SLICE0_F4;
         i += A_THREADS) {
        __stcs(&out[i], z);
    }
}

// ---------------------------------------------------------------------------
// Kernel B (fused, R4-proven shape): 1,048,576 threads (4096 x 256).
//   Each thread:
//     1. issues its scatter input loads (coords + feature quad) up front,
//     2. streams zeros into slices 1..7 (__stcs evict-first; the load
//        latency hides under these independent stores),
//     3. fires one red.global.add.v4.f32 into batch slice 0 mid-stream,
//     4. finishes its zero stripe.
// Scatter semantics (faithful to the reference):
//   - ALL B*N points land in batch slice 0 (reference's tf.zeros batch column)
//   - round-half-to-even via __float2int_rn (jnp.round)
//   - out-of-box points contribute exactly +0.0 -> skipped
// ---------------------------------------------------------------------------
__global__ void __launch_bounds__(256)
fused_scatter_zero_kernel(const float* __restrict__ coords,
                          const float4* __restrict__ features4,
                          float* __restrict__ out) {
    const int tid = blockIdx.x * blockDim.x + threadIdx.x;

    const int p = tid >> 3;        // global point index (b*N + n)
    const int q = tid & 7;         // which float4 of the 8 covering F=32

    // Issue all scatter inputs NOW; consumed after 6 store batches so the
    // DRAM latency hides under the streaming stores.
    float c0 = __ldg(&coords[p * 3 + 0]);
    float c1 = __ldg(&coords[p * 3 + 1]);
    float c2 = __ldg(&coords[p * 3 + 2]);
    float4 v = __ldg(&features4[(long long)p * 8 + q]);

    float4* out4 = (float4*)out;
    const float4 z = make_float4(0.f, 0.f, 0.f, 0.f);

    long long i = (long long)SLICE0_F4 + tid;

    #pragma unroll
    for (int k = 0; k < 6; k++) {
        if (i < TOTAL_F4) { __stcs(&out4[i], z); }
        i += NTHREADS;
    }

    // Scatter: loads have landed; fire-and-forget vector reduction.
    {
        int g0 = __float2int_rn(c0 + MAX_DIST);
        int g1 = __float2int_rn(c1 + MAX_DIST);
        int g2 = __float2int_rn(c2 + MAX_DIST);
        if ((unsigned)g0 < BOX && (unsigned)g1 < BOX && (unsigned)g2 < BOX) {
            int cell = (g0 * BOX + g1) * BOX + g2;
            float* dst = out + (long long)cell * FDIM + q * 4;  // slice 0
            asm volatile("red.global.add.v4.f32 [%0], {%1, %2, %3, %4};"
                         :: "l"(dst), "f"(v.x), "f"(v.y), "f"(v.z), "f"(v.w)
                         : "memory");
        }
    }

    // Remaining zero stores.
    for (; i < TOTAL_F4; i += NTHREADS) {
        __stcs(&out4[i], z);
    }
}

extern "C" void kernel_launch(void* const* d_in, const int* in_sizes, int n_in,
                              void* d_out, int out_size) {
    const float* coords = (const float*)d_in[0];     // [8,16384,3] f32
    const float4* feats = (const float4*)d_in[1];    // [8,16384,32] f32 as float4
    float* out = (float*)d_out;                      // [8,71,71,71,32] f32

    // Kernel A: streaming-zero slice 0 (ordering dep for the atomics).
    zero_slice0_kernel<<<A_BLOCKS, 256>>>((float4*)out);

    // Kernel B: fused scatter + zero of slices 1..7.
    fused_scatter_zero_kernel<<<SCATTER_WORK / 256, 256>>>(coords, feats, out);
}

// round 9
// speedup vs baseline: 1.0355x; 1.0005x over previous
#include <cuda_runtime.h>
#include <cstdint>

// Problem constants
#define MAX_DIST 35.0f
#define BOX 71            // ceil(2*35/1 + 1)
#define FDIM 32
#define BATCH 8
#define NPTS 16384

// Derived sizes (in float4 units)
#define SLICE0_F4 (BOX * BOX * BOX * FDIM / 4)          // 2,863,288
#define TOTAL_F4  (BATCH * BOX * BOX * BOX * FDIM / 4)  // 22,906,304
#define SCATTER_WORK (BATCH * NPTS * (FDIM / 4))        // 1,048,576 point-quads
#define NTHREADS SCATTER_WORK                           // 1 scatter item / thread

#define A_BLOCKS (148 * 8)                              // one full wave
#define A_THREADS (A_BLOCKS * 256)

// ---------------------------------------------------------------------------
// Kernel A: zero batch slice 0 (45.8 MB) with streaming stores. Its full
// completion (implicit PDL trigger at kernel end) releases kernel B's
// cudaGridDependencySynchronize(), with all stores visible.
// ---------------------------------------------------------------------------
__global__ void __launch_bounds__(256)
zero_slice0_kernel(float4* __restrict__ out) {
    const float4 z = make_float4(0.f, 0.f, 0.f, 0.f);
    for (int i = blockIdx.x * blockDim.x + threadIdx.x; i < SLICE0_F4;
         i += A_THREADS) {
        __stcs(&out[i], z);
    }
}

// ---------------------------------------------------------------------------
// Kernel B (fused, PDL early-launch): 1,048,576 threads (4096 x 256).
//   Launched with programmaticStreamSerializationAllowed -> goes resident
//   while A still runs. Per thread:
//     1. issue scatter input loads (coords + feature quad),
//     2. stream 6 batches of zeros into slices 1..7 (independent of A;
//        overlaps A's runtime and hides the load latency),
//     3. cudaGridDependencySynchronize()  -- wait for A's zeros,
//     4. fire one red.global.add.v4.f32 into batch slice 0,
//     5. finish the zero stripe.
// Scatter semantics (faithful to the reference):
//   - ALL B*N points land in batch slice 0 (reference's tf.zeros batch column)
//   - round-half-to-even via __float2int_rn (jnp.round)
//   - out-of-box points contribute exactly +0.0 -> skipped
// ---------------------------------------------------------------------------
__global__ void __launch_bounds__(256)
fused_scatter_zero_kernel(const float* __restrict__ coords,
                          const float4* __restrict__ features4,
                          float* __restrict__ out) {
    const int tid = blockIdx.x * blockDim.x + threadIdx.x;

    const int p = tid >> 3;        // global point index (b*N + n)
    const int q = tid & 7;         // which float4 of the 8 covering F=32

    // Scatter inputs issued up front; latency hides under the stores below.
    float c0 = __ldg(&coords[p * 3 + 0]);
    float c1 = __ldg(&coords[p * 3 + 1]);
    float c2 = __ldg(&coords[p * 3 + 2]);
    float4 v = __ldg(&features4[(long long)p * 8 + q]);

    float4* out4 = (float4*)out;
    const float4 z = make_float4(0.f, 0.f, 0.f, 0.f);

    long long i = (long long)SLICE0_F4 + tid;

    // Pre-dependency work: ~96 MB of zero stores across the grid, running
    // concurrently with kernel A.
    #pragma unroll
    for (int k = 0; k < 6; k++) {
        if (i < TOTAL_F4) { __stcs(&out4[i], z); }
        i += NTHREADS;
    }

    // Wait for kernel A's slice-0 zeros (PDL; all of A's stores visible).
    cudaGridDependencySynchronize();

    // Scatter: fire-and-forget vector reduction.
    {
        int g0 = __float2int_rn(c0 + MAX_DIST);
        int g1 = __float2int_rn(c1 + MAX_DIST);
        int g2 = __float2int_rn(c2 + MAX_DIST);
        if ((unsigned)g0 < BOX && (unsigned)g1 < BOX && (unsigned)g2 < BOX) {
            int cell = (g0 * BOX + g1) * BOX + g2;
            float* dst = out + (long long)cell * FDIM + q * 4;  // slice 0
            asm volatile("red.global.add.v4.f32 [%0], {%1, %2, %3, %4};"
                         :: "l"(dst), "f"(v.x), "f"(v.y), "f"(v.z), "f"(v.w)
                         : "memory");
        }
    }

    // Remaining zero stores.
    for (; i < TOTAL_F4; i += NTHREADS) {
        __stcs(&out4[i], z);
    }
}

extern "C" void kernel_launch(void* const* d_in, const int* in_sizes, int n_in,
                              void* d_out, int out_size) {
    const float* coords = (const float*)d_in[0];     // [8,16384,3] f32
    const float4* feats = (const float4*)d_in[1];    // [8,16384,32] f32 as float4
    float* out = (float*)d_out;                      // [8,71,71,71,32] f32

    // Kernel A: streaming-zero slice 0.
    zero_slice0_kernel<<<A_BLOCKS, 256>>>((float4*)out);

    // Kernel B: PDL early launch — overlaps A, syncs only before the atomics.
    cudaLaunchConfig_t cfg = {};
    cfg.gridDim = dim3(SCATTER_WORK / 256, 1, 1);
    cfg.blockDim = dim3(256, 1, 1);
    cfg.dynamicSmemBytes = 0;
    cudaLaunchAttribute attr[1];
    attr[0].id = cudaLaunchAttributeProgrammaticStreamSerialization;
    attr[0].val.programmaticStreamSerializationAllowed = 1;
    cfg.attrs = attr;
    cfg.numAttrs = 1;
    cudaLaunchKernelEx(&cfg, fused_scatter_zero_kernel, coords, feats, out);
}